// round 1
// baseline (speedup 1.0000x reference)
#include <cuda_runtime.h>
#include <cuda_fp16.h>
#include <cstdint>

#define TOKENS 4096
#define DIN    1024
#define DHID   4096
#define DOUT   1024
#define NEXP   8

// ---------------- device scratch (static allocation — no cudaMalloc) ----------------
__device__ __half g_xh [TOKENS * DIN];                       // x in fp16
__device__ __half g_B1 [(NEXP + 1) * DIN * DHID];            // W1 (e=0..7) + Wg1 (e=8), fp16
__device__ __half g_W2h[NEXP * DHID * DOUT];                 // W2 flattened [32768,1024], fp16
__device__ __half g_H  [(NEXP + 1) * (size_t)TOKENS * DHID]; // H[e][b][h]; slot 8 = gating hidden
__device__ float  g_gate[TOKENS * NEXP];                     // softmax gates

// ---------------- small helpers ----------------
__device__ __forceinline__ void cp_async16(unsigned dst, const void* src) {
    asm volatile("cp.async.cg.shared.global [%0], [%1], 16;\n" :: "r"(dst), "l"(src));
}
__device__ __forceinline__ void cp_commit() {
    asm volatile("cp.async.commit_group;\n" ::: "memory");
}
__device__ __forceinline__ void cp_wait2() {
    asm volatile("cp.async.wait_group 2;\n" ::: "memory");
}
__device__ __forceinline__ void ldsm_x4(uint32_t* r, unsigned addr) {
    asm volatile("ldmatrix.sync.aligned.m8n8.x4.shared.b16 {%0,%1,%2,%3}, [%4];\n"
                 : "=r"(r[0]), "=r"(r[1]), "=r"(r[2]), "=r"(r[3]) : "r"(addr));
}
__device__ __forceinline__ void ldsm_x4_t(uint32_t* r, unsigned addr) {
    asm volatile("ldmatrix.sync.aligned.m8n8.x4.trans.shared.b16 {%0,%1,%2,%3}, [%4];\n"
                 : "=r"(r[0]), "=r"(r[1]), "=r"(r[2]), "=r"(r[3]) : "r"(addr));
}
__device__ __forceinline__ void mma16816(float* c, const uint32_t* a, uint32_t b0, uint32_t b1) {
    asm volatile("mma.sync.aligned.m16n8k16.row.col.f32.f16.f16.f32 "
                 "{%0,%1,%2,%3},{%4,%5,%6,%7},{%8,%9},{%0,%1,%2,%3};\n"
                 : "+f"(c[0]), "+f"(c[1]), "+f"(c[2]), "+f"(c[3])
                 : "r"(a[0]), "r"(a[1]), "r"(a[2]), "r"(a[3]), "r"(b0), "r"(b1));
}

// ---------------- fp32 -> fp16 convert ----------------
__global__ void cvt_f32_f16(const float* __restrict__ src, __half* __restrict__ dst, int n) {
    int i = (blockIdx.x * blockDim.x + threadIdx.x) * 4;
    if (i >= n) return;
    float4 v = *(const float4*)(src + i);
    *(__half2*)(dst + i)     = __floats2half2_rn(v.x, v.y);
    *(__half2*)(dst + i + 2) = __floats2half2_rn(v.z, v.w);
}

// ---------------- gating logits + softmax ----------------
// One warp per token row; Wg2 transposed into smem for conflict-free LDS.
__global__ void __launch_bounds__(256) gate_kernel(
    const __half* __restrict__ Hg,     // [4096][4096] fp16 (gating hidden, relu'd)
    const float*  __restrict__ Wg2,    // [4096][8]
    const float*  __restrict__ bg2,    // [8]
    float* __restrict__ gate)          // [4096][8]
{
    extern __shared__ float sW[];      // [8][4096] (transposed)
    const int tid = threadIdx.x;
    for (int i = tid; i < DHID * NEXP; i += 256) {
        int k = i >> 3, j = i & 7;
        sW[j * DHID + k] = Wg2[i];
    }
    __syncthreads();

    const int warp = tid >> 5, lane = tid & 31;
    const int row = blockIdx.x * 8 + warp;
    const __half* h = Hg + (long long)row * DHID;

    float a[NEXP];
#pragma unroll
    for (int j = 0; j < NEXP; j++) a[j] = 0.f;

    for (int k = lane; k < DHID; k += 32) {
        float x = __half2float(h[k]);
#pragma unroll
        for (int j = 0; j < NEXP; j++) a[j] += x * sW[j * DHID + k];
    }
#pragma unroll
    for (int j = 0; j < NEXP; j++)
#pragma unroll
        for (int o = 16; o > 0; o >>= 1)
            a[j] += __shfl_xor_sync(0xffffffffu, a[j], o);

    float m = -1e30f;
#pragma unroll
    for (int j = 0; j < NEXP; j++) { a[j] += bg2[j]; m = fmaxf(m, a[j]); }
    float ex[NEXP], s = 0.f;
#pragma unroll
    for (int j = 0; j < NEXP; j++) { ex[j] = expf(a[j] - m); s += ex[j]; }
    if (lane < NEXP) gate[row * NEXP + lane] = ex[lane] / s;
}

// ---------------- fused fp16 GEMM ----------------
// MODE 0: C = relu(A@B + bias)                 -> fp16   (gating layer-1)
// MODE 1: C = gate[b,e] * relu(A@B + bias)     -> fp16   (expert layer-1, batched over e)
// MODE 2: C = A@B + sum_j gate[b,j]*b2[j,:]    -> fp32   (layer-2, K=32768)
constexpr int BM = 128, BN = 128, BK = 64, STAGES = 3;
constexpr int ASTR = BK + 8;          // 72 halves (144 B rows: conflict-free ldmatrix)
constexpr int BSTR = BN + 8;          // 136 halves (272 B rows)
constexpr int A_TILE = BM * ASTR;     // halves
constexpr int B_TILE = BK * BSTR;
constexpr int SMEM_BYTES = STAGES * (A_TILE + B_TILE) * 2;  // 107,520 B

template <int MODE>
__global__ void __launch_bounds__(256) moe_gemm(
    const __half* __restrict__ A, long long aEStride, int lda,
    const __half* __restrict__ Bbase, long long bStride, int ldb,
    const float* __restrict__ biasBase, long long biasStride,
    const float* __restrict__ gate,
    void* __restrict__ Cbase, long long cStride, int ldc,
    int K)
{
    extern __shared__ __half sm_[];
    __half* As = sm_;
    __half* Bs = sm_ + STAGES * A_TILE;

    const int tid  = threadIdx.x;
    const int lane = tid & 31;
    const int warp = tid >> 5;
    const int wm = warp >> 1, wn = warp & 1;   // 4x2 warp grid, warp tile 32x64
    const int bm0 = blockIdx.y * BM;
    const int bn0 = blockIdx.x * BN;
    const int e   = blockIdx.z;

    const __half* Bmat = Bbase + (long long)e * bStride;
    const float*  bias = biasBase + (long long)e * biasStride;

    const unsigned sA0 = (unsigned)__cvta_generic_to_shared(As);
    const unsigned sB0 = (unsigned)__cvta_generic_to_shared(Bs);

    float acc[2][8][4];
#pragma unroll
    for (int a = 0; a < 2; a++)
#pragma unroll
        for (int b = 0; b < 8; b++)
#pragma unroll
            for (int c = 0; c < 4; c++) acc[a][b][c] = 0.f;

    const int KT = K / BK;

    auto load_tile = [&](int kt, int buf) {
        const int k0 = kt * BK;
        // A may be blocked per expert along K (MODE 2): e = k0>>12 selects the H slab.
        const __half* aSrc = A + ((long long)(k0 >> 12)) * aEStride + (k0 & 4095);
        const __half* bSrc = Bmat + (long long)k0 * ldb + bn0;
        const unsigned da = sA0 + buf * (A_TILE * 2);
        const unsigned db = sB0 + buf * (B_TILE * 2);
#pragma unroll
        for (int i = 0; i < 4; i++) {
            int c = tid + i * 256;
            int r = c >> 3, c8 = (c & 7) << 3;
            cp_async16(da + (unsigned)(r * ASTR + c8) * 2,
                       aSrc + (long long)(bm0 + r) * lda + c8);
        }
#pragma unroll
        for (int i = 0; i < 4; i++) {
            int c = tid + i * 256;
            int r = c >> 4, c16 = (c & 15) << 3;
            cp_async16(db + (unsigned)(r * BSTR + c16) * 2,
                       bSrc + (long long)r * ldb + c16);
        }
        cp_commit();
    };

    load_tile(0, 0);
    load_tile(1, 1);

    const int lr = lane & 15;
    const int lc = (lane >> 4) << 3;

    for (int kt = 0; kt < KT; kt++) {
        if (kt + 2 < KT) load_tile(kt + 2, (kt + 2) % STAGES);
        else             cp_commit();
        cp_wait2();
        __syncthreads();

        const int buf = kt % STAGES;
        const unsigned aB = sA0 + buf * (A_TILE * 2);
        const unsigned bB = sB0 + buf * (B_TILE * 2);
#pragma unroll
        for (int ks = 0; ks < BK / 16; ks++) {
            uint32_t af[2][4];
#pragma unroll
            for (int mb = 0; mb < 2; mb++)
                ldsm_x4(af[mb], aB + (unsigned)((wm * 32 + mb * 16 + lr) * ASTR + ks * 16 + lc) * 2);
            uint32_t bf[4][4];
#pragma unroll
            for (int nb = 0; nb < 4; nb++)
                ldsm_x4_t(bf[nb], bB + (unsigned)((ks * 16 + lr) * BSTR + wn * 64 + nb * 16 + lc) * 2);
#pragma unroll
            for (int mb = 0; mb < 2; mb++)
#pragma unroll
                for (int nb = 0; nb < 4; nb++) {
                    mma16816(acc[mb][2 * nb],     af[mb], bf[nb][0], bf[nb][1]);
                    mma16816(acc[mb][2 * nb + 1], af[mb], bf[nb][2], bf[nb][3]);
                }
        }
        __syncthreads();
    }

    // -------- epilogue --------
    const int g  = lane >> 2;
    const int tg = lane & 3;

    if constexpr (MODE == 0 || MODE == 1) {
        __half* C = (__half*)Cbase + (long long)e * cStride;
#pragma unroll
        for (int mb = 0; mb < 2; mb++)
#pragma unroll
            for (int i = 0; i < 2; i++) {
                const int row = bm0 + wm * 32 + mb * 16 + g + i * 8;
                float gv = 1.f;
                if constexpr (MODE == 1) gv = gate[row * NEXP + e];
#pragma unroll
                for (int nb = 0; nb < 8; nb++) {
                    const int col = bn0 + wn * 64 + nb * 8 + tg * 2;
                    float v0 = fmaxf(acc[mb][nb][2 * i + 0] + bias[col],     0.f);
                    float v1 = fmaxf(acc[mb][nb][2 * i + 1] + bias[col + 1], 0.f);
                    if constexpr (MODE == 1) { v0 *= gv; v1 *= gv; }
                    *(__half2*)(C + (long long)row * ldc + col) = __floats2half2_rn(v0, v1);
                }
            }
    } else {
        float* C = (float*)Cbase;
#pragma unroll
        for (int nb = 0; nb < 8; nb++) {
            const int col = bn0 + wn * 64 + nb * 8 + tg * 2;
            float b0c[NEXP], b1c[NEXP];
#pragma unroll
            for (int j = 0; j < NEXP; j++) {
                b0c[j] = bias[j * DOUT + col];
                b1c[j] = bias[j * DOUT + col + 1];
            }
#pragma unroll
            for (int mb = 0; mb < 2; mb++)
#pragma unroll
                for (int i = 0; i < 2; i++) {
                    const int row = bm0 + wm * 32 + mb * 16 + g + i * 8;
                    const float* gr = gate + row * NEXP;
                    float s0 = 0.f, s1 = 0.f;
#pragma unroll
                    for (int j = 0; j < NEXP; j++) { s0 += gr[j] * b0c[j]; s1 += gr[j] * b1c[j]; }
                    float2 o;
                    o.x = acc[mb][nb][2 * i + 0] + s0;
                    o.y = acc[mb][nb][2 * i + 1] + s1;
                    *(float2*)(C + (long long)row * ldc + col) = o;
                }
        }
    }
}

// ---------------- launch ----------------
extern "C" void kernel_launch(void* const* d_in, const int* in_sizes, int n_in,
                              void* d_out, int out_size)
{
    const float* x   = (const float*)d_in[0];
    const float* W1  = (const float*)d_in[1];
    const float* b1  = (const float*)d_in[2];
    const float* W2  = (const float*)d_in[3];
    const float* b2  = (const float*)d_in[4];
    const float* Wg1 = (const float*)d_in[5];
    const float* bg1 = (const float*)d_in[6];
    const float* Wg2 = (const float*)d_in[7];
    const float* bg2 = (const float*)d_in[8];

    __half *xh, *B1, *W2h, *H;
    float* gate;
    cudaGetSymbolAddress((void**)&xh,   g_xh);
    cudaGetSymbolAddress((void**)&B1,   g_B1);
    cudaGetSymbolAddress((void**)&W2h,  g_W2h);
    cudaGetSymbolAddress((void**)&H,    g_H);
    cudaGetSymbolAddress((void**)&gate, g_gate);

    cudaFuncSetAttribute(moe_gemm<0>, cudaFuncAttributeMaxDynamicSharedMemorySize, SMEM_BYTES);
    cudaFuncSetAttribute(moe_gemm<1>, cudaFuncAttributeMaxDynamicSharedMemorySize, SMEM_BYTES);
    cudaFuncSetAttribute(moe_gemm<2>, cudaFuncAttributeMaxDynamicSharedMemorySize, SMEM_BYTES);
    cudaFuncSetAttribute(gate_kernel, cudaFuncAttributeMaxDynamicSharedMemorySize, DHID * NEXP * 4);

    // fp32 -> fp16 converts
    cvt_f32_f16<<<TOKENS * DIN / 1024, 256>>>(x, xh, TOKENS * DIN);
    cvt_f32_f16<<<NEXP * DIN * DHID / 1024, 256>>>(W1, B1, NEXP * DIN * DHID);
    cvt_f32_f16<<<DIN * DHID / 1024, 256>>>(Wg1, B1 + (long long)NEXP * DIN * DHID, DIN * DHID);
    cvt_f32_f16<<<NEXP * DHID * DOUT / 1024, 256>>>(W2, W2h, NEXP * DHID * DOUT);

    // 1) gating layer-1: Hg = relu(x @ Wg1 + bg1)  (slot 8)
    dim3 g0(DHID / BN, TOKENS / BM, 1);
    moe_gemm<0><<<g0, 256, SMEM_BYTES>>>(
        xh, 0, DIN,
        B1 + (long long)NEXP * DIN * DHID, 0, DHID,
        bg1, 0, nullptr,
        H + (long long)NEXP * TOKENS * DHID, 0, DHID, DIN);

    // 2) gates = softmax(Hg @ Wg2 + bg2)
    gate_kernel<<<TOKENS / 8, 256, DHID * NEXP * 4>>>(
        H + (long long)NEXP * TOKENS * DHID, Wg2, bg2, gate);

    // 3) expert layer-1 (batched over e): H[e] = gate[b,e] * relu(x @ W1[e] + b1[e])
    dim3 g1(DHID / BN, TOKENS / BM, NEXP);
    moe_gemm<1><<<g1, 256, SMEM_BYTES>>>(
        xh, 0, DIN,
        B1, (long long)DIN * DHID, DHID,
        b1, DHID, gate,
        H, (long long)TOKENS * DHID, DHID, DIN);

    // 4) layer-2 as one K=32768 GEMM: out = Hflat @ W2flat + gate @ b2
    dim3 g2(DOUT / BN, TOKENS / BM, 1);
    moe_gemm<2><<<g2, 256, SMEM_BYTES>>>(
        H, (long long)TOKENS * DHID, DHID,
        W2h, 0, DOUT,
        b2, 0, gate,
        d_out, 0, DOUT, NEXP * DHID);
}